// round 8
// baseline (speedup 1.0000x reference)
#include <cuda_runtime.h>

// out[b] = x[b,:]·(sum_o W[o,:]) + sum(b)
// Single persistent kernel, 1024 all-resident blocks, software grid barriers.
// Phase A: column-reduce W (64 MB) -> partials (4 MB)
// Phase B: 512 blocks reduce partials -> w_sum[2048]; 1 block sums bias
// Phase C: one dot per batch row (128 MB)

#define IN_F   2048
#define OUT_F  8192
#define BATCH  16384
#define VEC4   (IN_F / 4)                      // 512 float4 per row
#define RGROUPS 512
#define ROWS_PER_RG (OUT_F / RGROUPS)          // 16
#define NBLOCKS 1024

__device__ float g_partial[RGROUPS * IN_F];    // 4 MB scratch (deterministic 2-pass)
__device__ float g_wsum[IN_F];
__device__ float g_bsum;
__device__ unsigned g_count = 0;               // self-resetting: replay-safe
__device__ volatile unsigned g_gen = 0;        // monotone generation

__device__ __forceinline__ void grid_barrier() {
    __syncthreads();
    if (threadIdx.x == 0) {
        __threadfence();                       // publish my writes
        unsigned gen = g_gen;
        if (atomicAdd(&g_count, 1) == NBLOCKS - 1) {
            g_count = 0;
            __threadfence();
            g_gen = gen + 1;                   // release
        } else {
            while (g_gen == gen) __nanosleep(32);
        }
        __threadfence();                       // acquire
    }
    __syncthreads();
}

__global__ __launch_bounds__(256, 8) void fused_kernel(const float* __restrict__ x,
                                                       const float* __restrict__ W,
                                                       const float* __restrict__ b,
                                                       float* __restrict__ out) {
    __shared__ float4 s_buf[VEC4];             // 8 KB, reused across phases
    const int tid = threadIdx.x;
    const int bid = blockIdx.x;

    // ================= Phase A: W column partials =================
    {
        int col4 = (bid & 1) * 256 + tid;      // 0..511
        int rg   = bid >> 1;                   // 0..511
        const float4* W4 = reinterpret_cast<const float4*>(W)
                           + (size_t)rg * ROWS_PER_RG * VEC4 + col4;
        float4 acc = make_float4(0.f, 0.f, 0.f, 0.f);
        #pragma unroll
        for (int bt = 0; bt < 4; bt++) {
            float4 v[4];
            #pragma unroll
            for (int i = 0; i < 4; i++)
                v[i] = W4[(size_t)(bt * 4 + i) * VEC4];   // 4 loads in flight
            #pragma unroll
            for (int i = 0; i < 4; i++) {
                acc.x += v[i].x; acc.y += v[i].y; acc.z += v[i].z; acc.w += v[i].w;
            }
        }
        reinterpret_cast<float4*>(g_partial)[rg * VEC4 + col4] = acc;
    }

    grid_barrier();

    // ================= Phase B: finalize w_sum (512 blocks) + bias (1 block) ====
    if (bid < 512) {
        // This block owns col4 = bid: reduce 512 rowgroup partials.
        const float4* P4 = reinterpret_cast<const float4*>(g_partial);
        float4 a0 = P4[(size_t)tid * VEC4 + bid];
        float4 a1 = P4[(size_t)(tid + 256) * VEC4 + bid];
        float4 acc;
        acc.x = a0.x + a1.x; acc.y = a0.y + a1.y;
        acc.z = a0.z + a1.z; acc.w = a0.w + a1.w;
        s_buf[tid] = acc;
        __syncthreads();
        #pragma unroll
        for (int o = 128; o > 0; o >>= 1) {
            if (tid < o) {
                float4 t = s_buf[tid + o];
                float4 m = s_buf[tid];
                m.x += t.x; m.y += t.y; m.z += t.z; m.w += t.w;
                s_buf[tid] = m;
            }
            __syncthreads();
        }
        if (tid == 0)
            reinterpret_cast<float4*>(g_wsum)[bid] = s_buf[0];
    } else if (bid == 512) {
        float* s_f = reinterpret_cast<float*>(s_buf);
        float s = 0.f;
        for (int i = tid; i < OUT_F; i += 256) s += b[i];
        s_f[tid] = s;
        __syncthreads();
        #pragma unroll
        for (int o = 128; o > 0; o >>= 1) {
            if (tid < o) s_f[tid] += s_f[tid + o];
            __syncthreads();
        }
        if (tid == 0) g_bsum = s_f[0];
    }

    grid_barrier();

    // ================= Phase C: dot per batch row =================
    {
        const float4* Wsum4 = reinterpret_cast<const float4*>(g_wsum);
        s_buf[tid]       = Wsum4[tid];
        s_buf[tid + 256] = Wsum4[tid + 256];
        __syncthreads();

        int warp = tid >> 5;
        int lane = tid & 31;
        int base = bid * 16;

        float res[2];
        #pragma unroll
        for (int rr = 0; rr < 2; rr++) {
            int row = base + rr * 8 + warp;
            const float4* x4 = reinterpret_cast<const float4*>(x)
                               + (size_t)row * VEC4 + lane;
            float acc = 0.f;
            #pragma unroll
            for (int bt = 0; bt < 4; bt++) {
                float4 v[4];
                #pragma unroll
                for (int i = 0; i < 4; i++)
                    v[i] = x4[(bt * 4 + i) * 32];         // 4 loads in flight
                #pragma unroll
                for (int i = 0; i < 4; i++) {
                    float4 w = s_buf[(bt * 4 + i) * 32 + lane];
                    acc += v[i].x * w.x + v[i].y * w.y + v[i].z * w.z + v[i].w * w.w;
                }
            }
            #pragma unroll
            for (int o = 16; o > 0; o >>= 1)
                acc += __shfl_xor_sync(0xffffffffu, acc, o);
            res[rr] = acc;
        }

        if (lane == 0) {
            float bs = g_bsum;
            out[base + warp]     = res[0] + bs;
            out[base + 8 + warp] = res[1] + bs;
        }
    }
}

extern "C" void kernel_launch(void* const* d_in, const int* in_sizes, int n_in,
                              void* d_out, int out_size) {
    const float* x = (const float*)d_in[0];   // [16384, 2048]
    const float* W = (const float*)d_in[1];   // [8192, 2048]
    const float* b = (const float*)d_in[2];   // [8192]
    float* out = (float*)d_out;               // [16384, 1]
    (void)in_sizes; (void)n_in; (void)out_size;

    fused_kernel<<<NBLOCKS, 256>>>(x, W, b, out);
}

// round 9
// speedup vs baseline: 1.0056x; 1.0056x over previous
#include <cuda_runtime.h>

// out[b] = x[b,:]·(sum_o W[o,:]) + sum(b)
// Single persistent kernel, 1024 all-resident blocks, software grid barriers.
// Phase A: column-reduce W (64 MB) -> partials (4 MB)
// Phase B: 512 blocks reduce partials -> w_sum[2048]; 1 block sums bias
// Phase C: one dot per batch row (128 MB)

#define IN_F   2048
#define OUT_F  8192
#define BATCH  16384
#define VEC4   (IN_F / 4)                      // 512 float4 per row
#define RGROUPS 512
#define ROWS_PER_RG (OUT_F / RGROUPS)          // 16
#define NBLOCKS 1024

__device__ float g_partial[RGROUPS * IN_F];    // 4 MB scratch (deterministic 2-pass)
__device__ float g_wsum[IN_F];
__device__ float g_bsum;
__device__ unsigned g_count = 0;               // self-resetting: replay-safe
__device__ volatile unsigned g_gen = 0;        // monotone generation

__device__ __forceinline__ void grid_barrier() {
    __syncthreads();
    if (threadIdx.x == 0) {
        __threadfence();                       // publish my writes
        unsigned gen = g_gen;
        if (atomicAdd(&g_count, 1) == NBLOCKS - 1) {
            g_count = 0;
            __threadfence();
            g_gen = gen + 1;                   // release
        } else {
            while (g_gen == gen) __nanosleep(32);
        }
        __threadfence();                       // acquire
    }
    __syncthreads();
}

__global__ __launch_bounds__(256, 8) void fused_kernel(const float* __restrict__ x,
                                                       const float* __restrict__ W,
                                                       const float* __restrict__ b,
                                                       float* __restrict__ out) {
    __shared__ float4 s_buf[VEC4];             // 8 KB, reused across phases
    const int tid = threadIdx.x;
    const int bid = blockIdx.x;

    // ================= Phase A: W column partials =================
    {
        int col4 = (bid & 1) * 256 + tid;      // 0..511
        int rg   = bid >> 1;                   // 0..511
        const float4* W4 = reinterpret_cast<const float4*>(W)
                           + (size_t)rg * ROWS_PER_RG * VEC4 + col4;
        float4 acc = make_float4(0.f, 0.f, 0.f, 0.f);
        #pragma unroll
        for (int bt = 0; bt < 4; bt++) {
            float4 v[4];
            #pragma unroll
            for (int i = 0; i < 4; i++)
                v[i] = W4[(size_t)(bt * 4 + i) * VEC4];   // 4 loads in flight
            #pragma unroll
            for (int i = 0; i < 4; i++) {
                acc.x += v[i].x; acc.y += v[i].y; acc.z += v[i].z; acc.w += v[i].w;
            }
        }
        reinterpret_cast<float4*>(g_partial)[rg * VEC4 + col4] = acc;
    }

    grid_barrier();

    // ================= Phase B: finalize w_sum (512 blocks) + bias (1 block) ====
    if (bid < 512) {
        // This block owns col4 = bid: reduce 512 rowgroup partials.
        const float4* P4 = reinterpret_cast<const float4*>(g_partial);
        float4 a0 = P4[(size_t)tid * VEC4 + bid];
        float4 a1 = P4[(size_t)(tid + 256) * VEC4 + bid];
        float4 acc;
        acc.x = a0.x + a1.x; acc.y = a0.y + a1.y;
        acc.z = a0.z + a1.z; acc.w = a0.w + a1.w;
        s_buf[tid] = acc;
        __syncthreads();
        #pragma unroll
        for (int o = 128; o > 0; o >>= 1) {
            if (tid < o) {
                float4 t = s_buf[tid + o];
                float4 m = s_buf[tid];
                m.x += t.x; m.y += t.y; m.z += t.z; m.w += t.w;
                s_buf[tid] = m;
            }
            __syncthreads();
        }
        if (tid == 0)
            reinterpret_cast<float4*>(g_wsum)[bid] = s_buf[0];
    } else if (bid == 512) {
        float* s_f = reinterpret_cast<float*>(s_buf);
        float s = 0.f;
        for (int i = tid; i < OUT_F; i += 256) s += b[i];
        s_f[tid] = s;
        __syncthreads();
        #pragma unroll
        for (int o = 128; o > 0; o >>= 1) {
            if (tid < o) s_f[tid] += s_f[tid + o];
            __syncthreads();
        }
        if (tid == 0) g_bsum = s_f[0];
    }

    grid_barrier();

    // ================= Phase C: dot per batch row =================
    {
        const float4* Wsum4 = reinterpret_cast<const float4*>(g_wsum);
        s_buf[tid]       = Wsum4[tid];
        s_buf[tid + 256] = Wsum4[tid + 256];
        __syncthreads();

        int warp = tid >> 5;
        int lane = tid & 31;
        int base = bid * 16;

        float res[2];
        #pragma unroll
        for (int rr = 0; rr < 2; rr++) {
            int row = base + rr * 8 + warp;
            const float4* x4 = reinterpret_cast<const float4*>(x)
                               + (size_t)row * VEC4 + lane;
            float acc = 0.f;
            #pragma unroll
            for (int bt = 0; bt < 4; bt++) {
                float4 v[4];
                #pragma unroll
                for (int i = 0; i < 4; i++)
                    v[i] = x4[(bt * 4 + i) * 32];         // 4 loads in flight
                #pragma unroll
                for (int i = 0; i < 4; i++) {
                    float4 w = s_buf[(bt * 4 + i) * 32 + lane];
                    acc += v[i].x * w.x + v[i].y * w.y + v[i].z * w.z + v[i].w * w.w;
                }
            }
            #pragma unroll
            for (int o = 16; o > 0; o >>= 1)
                acc += __shfl_xor_sync(0xffffffffu, acc, o);
            res[rr] = acc;
        }

        if (lane == 0) {
            float bs = g_bsum;
            out[base + warp]     = res[0] + bs;
            out[base + 8 + warp] = res[1] + bs;
        }
    }
}

extern "C" void kernel_launch(void* const* d_in, const int* in_sizes, int n_in,
                              void* d_out, int out_size) {
    const float* x = (const float*)d_in[0];   // [16384, 2048]
    const float* W = (const float*)d_in[1];   // [8192, 2048]
    const float* b = (const float*)d_in[2];   // [8192]
    float* out = (float*)d_out;               // [16384, 1]
    (void)in_sizes; (void)n_in; (void)out_size;

    fused_kernel<<<NBLOCKS, 256>>>(x, W, b, out);
}

// round 10
// speedup vs baseline: 1.0099x; 1.0042x over previous
#include <cuda_runtime.h>

// out[b] = x[b,:]·(sum_o W[o,:]) + sum(b)
// Single persistent kernel, 1024 all-resident blocks, software grid barriers.
// Phase A: column-reduce W (64 MB) -> partials (4 MB)
// Phase B: 512 blocks reduce partials -> w_sum[2048]; 1 block sums bias
// Phase C: one dot per batch row (128 MB)

#define IN_F   2048
#define OUT_F  8192
#define BATCH  16384
#define VEC4   (IN_F / 4)                      // 512 float4 per row
#define RGROUPS 512
#define ROWS_PER_RG (OUT_F / RGROUPS)          // 16
#define NBLOCKS 1024

__device__ float g_partial[RGROUPS * IN_F];    // 4 MB scratch (deterministic 2-pass)
__device__ float g_wsum[IN_F];
__device__ float g_bsum;
__device__ unsigned g_count = 0;               // self-resetting: replay-safe
__device__ volatile unsigned g_gen = 0;        // monotone generation

__device__ __forceinline__ void grid_barrier() {
    __syncthreads();
    if (threadIdx.x == 0) {
        __threadfence();                       // publish my writes
        unsigned gen = g_gen;
        if (atomicAdd(&g_count, 1) == NBLOCKS - 1) {
            g_count = 0;
            __threadfence();
            g_gen = gen + 1;                   // release
        } else {
            while (g_gen == gen) __nanosleep(32);
        }
        __threadfence();                       // acquire
    }
    __syncthreads();
}

__global__ __launch_bounds__(256, 8) void fused_kernel(const float* __restrict__ x,
                                                       const float* __restrict__ W,
                                                       const float* __restrict__ b,
                                                       float* __restrict__ out) {
    __shared__ float4 s_buf[VEC4];             // 8 KB, reused across phases
    const int tid = threadIdx.x;
    const int bid = blockIdx.x;

    // ================= Phase A: W column partials =================
    {
        int col4 = (bid & 1) * 256 + tid;      // 0..511
        int rg   = bid >> 1;                   // 0..511
        const float4* W4 = reinterpret_cast<const float4*>(W)
                           + (size_t)rg * ROWS_PER_RG * VEC4 + col4;
        float4 acc = make_float4(0.f, 0.f, 0.f, 0.f);
        #pragma unroll
        for (int bt = 0; bt < 4; bt++) {
            float4 v[4];
            #pragma unroll
            for (int i = 0; i < 4; i++)
                v[i] = W4[(size_t)(bt * 4 + i) * VEC4];   // 4 loads in flight
            #pragma unroll
            for (int i = 0; i < 4; i++) {
                acc.x += v[i].x; acc.y += v[i].y; acc.z += v[i].z; acc.w += v[i].w;
            }
        }
        reinterpret_cast<float4*>(g_partial)[rg * VEC4 + col4] = acc;
    }

    grid_barrier();

    // ================= Phase B: finalize w_sum (512 blocks) + bias (1 block) ====
    if (bid < 512) {
        // This block owns col4 = bid: reduce 512 rowgroup partials.
        const float4* P4 = reinterpret_cast<const float4*>(g_partial);
        float4 a0 = P4[(size_t)tid * VEC4 + bid];
        float4 a1 = P4[(size_t)(tid + 256) * VEC4 + bid];
        float4 acc;
        acc.x = a0.x + a1.x; acc.y = a0.y + a1.y;
        acc.z = a0.z + a1.z; acc.w = a0.w + a1.w;
        s_buf[tid] = acc;
        __syncthreads();
        #pragma unroll
        for (int o = 128; o > 0; o >>= 1) {
            if (tid < o) {
                float4 t = s_buf[tid + o];
                float4 m = s_buf[tid];
                m.x += t.x; m.y += t.y; m.z += t.z; m.w += t.w;
                s_buf[tid] = m;
            }
            __syncthreads();
        }
        if (tid == 0)
            reinterpret_cast<float4*>(g_wsum)[bid] = s_buf[0];
    } else if (bid == 512) {
        float* s_f = reinterpret_cast<float*>(s_buf);
        float s = 0.f;
        for (int i = tid; i < OUT_F; i += 256) s += b[i];
        s_f[tid] = s;
        __syncthreads();
        #pragma unroll
        for (int o = 128; o > 0; o >>= 1) {
            if (tid < o) s_f[tid] += s_f[tid + o];
            __syncthreads();
        }
        if (tid == 0) g_bsum = s_f[0];
    }

    grid_barrier();

    // ================= Phase C: dot per batch row =================
    {
        const float4* Wsum4 = reinterpret_cast<const float4*>(g_wsum);
        s_buf[tid]       = Wsum4[tid];
        s_buf[tid + 256] = Wsum4[tid + 256];
        __syncthreads();

        int warp = tid >> 5;
        int lane = tid & 31;
        int base = bid * 16;

        float res[2];
        #pragma unroll
        for (int rr = 0; rr < 2; rr++) {
            int row = base + rr * 8 + warp;
            const float4* x4 = reinterpret_cast<const float4*>(x)
                               + (size_t)row * VEC4 + lane;
            float acc = 0.f;
            #pragma unroll
            for (int bt = 0; bt < 4; bt++) {
                float4 v[4];
                #pragma unroll
                for (int i = 0; i < 4; i++)
                    v[i] = x4[(bt * 4 + i) * 32];         // 4 loads in flight
                #pragma unroll
                for (int i = 0; i < 4; i++) {
                    float4 w = s_buf[(bt * 4 + i) * 32 + lane];
                    acc += v[i].x * w.x + v[i].y * w.y + v[i].z * w.z + v[i].w * w.w;
                }
            }
            #pragma unroll
            for (int o = 16; o > 0; o >>= 1)
                acc += __shfl_xor_sync(0xffffffffu, acc, o);
            res[rr] = acc;
        }

        if (lane == 0) {
            float bs = g_bsum;
            out[base + warp]     = res[0] + bs;
            out[base + 8 + warp] = res[1] + bs;
        }
    }
}

extern "C" void kernel_launch(void* const* d_in, const int* in_sizes, int n_in,
                              void* d_out, int out_size) {
    const float* x = (const float*)d_in[0];   // [16384, 2048]
    const float* W = (const float*)d_in[1];   // [8192, 2048]
    const float* b = (const float*)d_in[2];   // [8192]
    float* out = (float*)d_out;               // [16384, 1]
    (void)in_sizes; (void)n_in; (void)out_size;

    fused_kernel<<<NBLOCKS, 256>>>(x, W, b, out);
}